// round 13
// baseline (speedup 1.0000x reference)
#include <cuda_runtime.h>
#include <cstdint>

// Problem constants
#define B_   2
#define S_   2048
#define D_   1024
#define H_   16
#define DK_  64
#define BH_  (B_*H_)          // 32
#define M_   (B_*S_)          // 4096

// ---------------- scratch (device globals; no allocations allowed) -------
__device__ float g_qh[BH_ * S_ * DK_];        // [B*H, S, DK] head-major (Q pre-scaled by 1/8)
__device__ float g_kh[BH_ * S_ * DK_];
__device__ float g_vh[BH_ * S_ * DK_];
__device__ float g_attn[M_ * D_];             // [B,S,D]

// ---------------- tf32 helpers ------------------------------------------
__device__ __forceinline__ uint32_t f2tf(float f) {
    uint32_t u;
    asm("cvt.rna.tf32.f32 %0, %1;" : "=r"(u) : "f"(f));
    return u;
}

__device__ __forceinline__ void mma8(float* c, const uint32_t* a, const uint32_t* b) {
    asm volatile(
        "mma.sync.aligned.m16n8k8.row.col.f32.tf32.tf32.f32 "
        "{%0,%1,%2,%3}, {%4,%5,%6,%7}, {%8,%9}, {%0,%1,%2,%3};\n"
        : "+f"(c[0]), "+f"(c[1]), "+f"(c[2]), "+f"(c[3])
        : "r"(a[0]), "r"(a[1]), "r"(a[2]), "r"(a[3]),
          "r"(b[0]), "r"(b[1]));
}

__device__ __forceinline__ uint32_t s2u(const void* p) {
    return (uint32_t)__cvta_generic_to_shared(p);
}

// ldmatrix x4: four 8x4-of-32bit tiles (b16 view), reg j fed by lanes 8j..8j+7
__device__ __forceinline__ void ldsm4(uint32_t* r, uint32_t addr) {
    asm volatile("ldmatrix.sync.aligned.m8n8.x4.shared.b16 {%0,%1,%2,%3}, [%4];"
                 : "=r"(r[0]), "=r"(r[1]), "=r"(r[2]), "=r"(r[3]) : "r"(addr));
}

// Padded strides (conflict-free): A-style ≡4 (mod 32), B-style ≡8 (mod 32)
#define SA_ 36
#define SB_ 136

// ============================================================
//  Projection / output GEMM (UNCHANGED from R12 — proven).
//  C[128,128] = X[.,1024] @ W[1024,.] + b ; 512 thr, warp 4x4, ping-pong.
//  DST: 0=g_qh(scaled 1/8) 1=g_kh 2=g_vh 3=direct to `out` (src g_attn)
// ============================================================
struct ProjSmem {
    uint32_t As[2][128][SA_];
    uint32_t Bs[2][32][SB_];
};

template<int DST>
__global__ void __launch_bounds__(512, 1) proj_tf32(
    const float* __restrict__ X, const float* __restrict__ W,
    const float* __restrict__ bias, float* __restrict__ out)
{
    extern __shared__ char smraw[];
    ProjSmem& sm = *reinterpret_cast<ProjSmem*>(smraw);

    const float* Xp = (DST == 3) ? (const float*)g_attn : X;

    const int tid  = threadIdx.x;
    const int warp = tid >> 5, lane = tid & 31;
    const int g = lane >> 2, tg = lane & 3;
    const int wm0 = (warp >> 2) * 32, wn0 = (warp & 3) * 32;
    const int m0 = blockIdx.y * 128, n0 = blockIdx.x * 128;

    const int ar = tid >> 3, aq = tid & 7;
    const int br = tid >> 5, bq = tid & 31;
    const float* Abase = Xp + (size_t)(m0 + ar) * 1024 + aq * 4;
    const float* A2    = Xp + (size_t)(m0 + 64 + ar) * 1024 + aq * 4;
    const float* Bbase = W + (size_t)br * 1024 + n0 + bq * 4;
    const float* B2    = W + (size_t)(br + 16) * 1024 + n0 + bq * 4;

    uint4 sa[2], sb[2];
    auto ldglobal = [&](int k0) {
        float4 v0 = *(const float4*)(Abase + k0);
        float4 v1 = *(const float4*)(A2 + k0);
        sa[0] = make_uint4(f2tf(v0.x), f2tf(v0.y), f2tf(v0.z), f2tf(v0.w));
        sa[1] = make_uint4(f2tf(v1.x), f2tf(v1.y), f2tf(v1.z), f2tf(v1.w));
        float4 w0 = *(const float4*)(Bbase + (size_t)k0 * 1024);
        float4 w1 = *(const float4*)(B2 + (size_t)k0 * 1024);
        sb[0] = make_uint4(f2tf(w0.x), f2tf(w0.y), f2tf(w0.z), f2tf(w0.w));
        sb[1] = make_uint4(f2tf(w1.x), f2tf(w1.y), f2tf(w1.z), f2tf(w1.w));
    };
    auto store = [&](int p) {
        *(uint4*)&sm.As[p][ar][aq * 4]       = sa[0];
        *(uint4*)&sm.As[p][64 + ar][aq * 4]  = sa[1];
        *(uint4*)&sm.Bs[p][br][bq * 4]       = sb[0];
        *(uint4*)&sm.Bs[p][16 + br][bq * 4]  = sb[1];
    };

    float acc[2][4][4] = {};

    ldglobal(0);
    store(0);
    __syncthreads();

    int p = 0;
    for (int k0 = 0; k0 < 1024; k0 += 32) {
        const bool more = (k0 + 32 < 1024);
        if (more) ldglobal(k0 + 32);
#pragma unroll
        for (int ks = 0; ks < 4; ks++) {
            const int kb = ks * 8;
            uint32_t a[2][4];
#pragma unroll
            for (int mi = 0; mi < 2; mi++) {
                int r = wm0 + mi * 16;
                a[mi][0] = sm.As[p][r + g][kb + tg];
                a[mi][1] = sm.As[p][r + g + 8][kb + tg];
                a[mi][2] = sm.As[p][r + g][kb + tg + 4];
                a[mi][3] = sm.As[p][r + g + 8][kb + tg + 4];
            }
#pragma unroll
            for (int ni = 0; ni < 4; ni++) {
                uint32_t b[2] = { sm.Bs[p][kb + tg][wn0 + ni * 8 + g],
                                  sm.Bs[p][kb + tg + 4][wn0 + ni * 8 + g] };
                mma8(acc[0][ni], a[0], b);
                mma8(acc[1][ni], a[1], b);
            }
        }
        if (more) store(p ^ 1);
        __syncthreads();
        p ^= 1;
    }

    float* dst = (DST == 0) ? g_qh : (DST == 1) ? g_kh : (DST == 2) ? g_vh : out;
#pragma unroll
    for (int mi = 0; mi < 2; mi++) {
#pragma unroll
        for (int rr = 0; rr < 2; rr++) {
            const int m = m0 + wm0 + mi * 16 + g + rr * 8;
#pragma unroll
            for (int ni = 0; ni < 4; ni++) {
                const int n = n0 + wn0 + ni * 8 + 2 * tg;
                float2 v;
                v.x = acc[mi][ni][rr * 2 + 0] + bias[n];
                v.y = acc[mi][ni][rr * 2 + 1] + bias[n + 1];
                if (DST == 0) { v.x *= 0.125f; v.y *= 0.125f; }
                if (DST == 3) {
                    *(float2*)&dst[(size_t)m * 1024 + n] = v;
                } else {
                    const int b = m >> 11, s = m & 2047;
                    const int h = n >> 6, d = n & 63;
                    *(float2*)&dst[((size_t)(b * H_ + h) * S_ + s) * DK_ + d] = v;
                }
            }
        }
    }
}

// ============================================================
//  Fused flash attention: softmax(QK^T + mask) @ V -> g_attn
//  Block: 128 q rows of one head, 256 threads, 8 warps (2x4).
//  Warp tile: 64x32 (S-phase), 64x16 over d (O-phase); mi=4.
//  Key loop: 16 tiles of 128 keys. ldmatrix.x4 for Q/K/P frags.
//  K tile at stride 68 and P tile (128x128, stride 132) share one region.
// ============================================================
#define SQ_ 68
#define SP_ 132
#define SV_ 72

struct FlashSmem {
    uint32_t Qs[128][SQ_];       // Q tile, A-style            (34816 B)
    uint32_t KP[128 * SP_];      // K (stride 68) / P (stride 132) (67584 B)
    uint32_t Vs[128][SV_];       // V tile, B-style            (36864 B)
    float sredm[4][128];
    float sreds[4][128];
    int   smask[128];
};

__global__ void __launch_bounds__(256, 1) flash_tf32(const int* __restrict__ mask)
{
    extern __shared__ char smem_raw[];
    FlashSmem& sm = *reinterpret_cast<FlashSmem*>(smem_raw);

    const int tid  = threadIdx.x;
    const int warp = tid >> 5, lane = tid & 31;
    const int g = lane >> 2, tg = lane & 3;
    const int wr = warp >> 2, wc = warp & 3;
    const int wm = wr * 64;
    const int i0 = blockIdx.x * 128;
    const int bh = blockIdx.y;
    const int bb = bh >> 4, h = bh & 15;

    const float* Q = g_qh + (size_t)bh * S_ * DK_;
    const float* K = g_kh + (size_t)bh * S_ * DK_;
    const float* V = g_vh + (size_t)bh * S_ * DK_;

    // ---- stage Q tile once (128 x 64, pre-scaled by 1/8) ----
#pragma unroll
    for (int i = 0; i < 8; i++) {
        int f = tid + 256 * i;
        int r = f >> 4, q4 = f & 15;
        float4 v = *(const float4*)(Q + (size_t)(i0 + r) * DK_ + q4 * 4);
        *(uint4*)&sm.Qs[r][q4 * 4] =
            make_uint4(f2tf(v.x), f2tf(v.y), f2tf(v.z), f2tf(v.w));
    }

    // ---- ldmatrix base addresses (byte addrs; advance 32B per ks) ----
    uint32_t qa[4], ka[2], pa[4];
#pragma unroll
    for (int mi = 0; mi < 4; mi++) {
        qa[mi] = s2u(&sm.Qs[wm + mi * 16 + (lane & 15)][(lane >> 4) * 4]);
        pa[mi] = s2u(&sm.KP[(size_t)(wm + mi * 16 + (lane & 15)) * SP_ + (lane >> 4) * 4]);
    }
#pragma unroll
    for (int pn = 0; pn < 2; pn++) {
        int row = wc * 32 + pn * 16 + ((lane >> 4) << 3) + (lane & 7);
        ka[pn] = s2u(&sm.KP[(size_t)row * SQ_ + (((lane >> 3) & 1) << 2)]);
    }

    float m_st[4][2], l_st[4][2];
    float acc_o[4][2][4] = {};
#pragma unroll
    for (int mi = 0; mi < 4; mi++)
#pragma unroll
        for (int rr = 0; rr < 2; rr++) { m_st[mi][rr] = -1e30f; l_st[mi][rr] = 0.f; }

    for (int t = 0; t < S_ / 128; t++) {
        const int j0 = t * 128;

        __syncthreads();   // previous tile's readers of KP/Vs/smask done
        // ---- stage K (A-style [key][k], stride 68) and V (B-style [k][d]) ----
#pragma unroll
        for (int i = 0; i < 8; i++) {
            int f = tid + 256 * i;
            int r = f >> 4, q4 = f & 15;
            float4 kv = *(const float4*)(K + (size_t)(j0 + r) * DK_ + q4 * 4);
            *(uint4*)&sm.KP[(size_t)r * SQ_ + q4 * 4] =
                make_uint4(f2tf(kv.x), f2tf(kv.y), f2tf(kv.z), f2tf(kv.w));
            float4 vv = *(const float4*)(V + (size_t)(j0 + r) * DK_ + q4 * 4);
            *(uint4*)&sm.Vs[r][q4 * 4] =
                make_uint4(f2tf(vv.x), f2tf(vv.y), f2tf(vv.z), f2tf(vv.w));
        }
        if (tid < 128) sm.smask[tid] = mask[bb * S_ + j0 + tid];
        __syncthreads();

        // ---- S = Q.K^T ; warp: rows [wm,wm+64), keys [wc*32,+32) ----
        float acc_s[4][4][4] = {};
#pragma unroll
        for (int ks = 0; ks < 8; ks++) {
            uint32_t a[4][4];
#pragma unroll
            for (int mi = 0; mi < 4; mi++) ldsm4(a[mi], qa[mi] + ks * 32);
#pragma unroll
            for (int pn = 0; pn < 2; pn++) {
                uint32_t b[4];
                ldsm4(b, ka[pn] + ks * 32);
#pragma unroll
                for (int mi = 0; mi < 4; mi++) {
                    mma8(acc_s[mi][2 * pn + 0], a[mi], &b[0]);
                    mma8(acc_s[mi][2 * pn + 1], a[mi], &b[2]);
                }
            }
        }

        // ---- mask + per-warp-col row max ----
#pragma unroll
        for (int mi = 0; mi < 4; mi++) {
#pragma unroll
            for (int rr = 0; rr < 2; rr++) {
                float mx = -1e30f;
#pragma unroll
                for (int ni = 0; ni < 4; ni++) {
#pragma unroll
                    for (int c = 0; c < 2; c++) {
                        const int col = wc * 32 + ni * 8 + 2 * tg + c;
                        float s = acc_s[mi][ni][rr * 2 + c];
                        s = sm.smask[col] ? -1e10f : s;
                        acc_s[mi][ni][rr * 2 + c] = s;
                        mx = fmaxf(mx, s);
                    }
                }
                mx = fmaxf(mx, __shfl_xor_sync(0xffffffffu, mx, 1));
                mx = fmaxf(mx, __shfl_xor_sync(0xffffffffu, mx, 2));
                if (tg == 0) sm.sredm[wc][wm + mi * 16 + rr * 8 + g] = mx;
            }
        }
        __syncthreads();   // S-mma done (KP free for P); sredm ready

        // ---- online softmax update; write P over KP (stride 132) ----
        float alpha[4][2];
#pragma unroll
        for (int mi = 0; mi < 4; mi++) {
#pragma unroll
            for (int rr = 0; rr < 2; rr++) {
                const int row = wm + mi * 16 + rr * 8 + g;
                float tm = fmaxf(fmaxf(sm.sredm[0][row], sm.sredm[1][row]),
                                 fmaxf(sm.sredm[2][row], sm.sredm[3][row]));
                float mn = fmaxf(m_st[mi][rr], tm);
                alpha[mi][rr] = __expf(m_st[mi][rr] - mn);
                m_st[mi][rr] = mn;
                float ps = 0.f;
#pragma unroll
                for (int ni = 0; ni < 4; ni++) {
#pragma unroll
                    for (int c = 0; c < 2; c++) {
                        float pv = __expf(acc_s[mi][ni][rr * 2 + c] - mn);
                        acc_s[mi][ni][rr * 2 + c] = pv;
                        ps += pv;
                    }
                }
                ps += __shfl_xor_sync(0xffffffffu, ps, 1);
                ps += __shfl_xor_sync(0xffffffffu, ps, 2);
                if (tg == 0) sm.sreds[wc][row] = ps;
#pragma unroll
                for (int ni = 0; ni < 4; ni++) {
                    uint2 u = make_uint2(f2tf(acc_s[mi][ni][rr * 2 + 0]),
                                         f2tf(acc_s[mi][ni][rr * 2 + 1]));
                    *(uint2*)&sm.KP[(size_t)row * SP_ + wc * 32 + ni * 8 + 2 * tg] = u;
                }
            }
        }
        // rescale O accumulator
#pragma unroll
        for (int mi = 0; mi < 4; mi++)
#pragma unroll
            for (int ni = 0; ni < 2; ni++)
#pragma unroll
                for (int e = 0; e < 4; e++)
                    acc_o[mi][ni][e] *= alpha[mi][e >> 1];
        __syncthreads();   // P tile + sreds complete

        // ---- l update ----
#pragma unroll
        for (int mi = 0; mi < 4; mi++) {
#pragma unroll
            for (int rr = 0; rr < 2; rr++) {
                const int row = wm + mi * 16 + rr * 8 + g;
                float ts = (sm.sreds[0][row] + sm.sreds[1][row]) +
                           (sm.sreds[2][row] + sm.sreds[3][row]);
                l_st[mi][rr] = l_st[mi][rr] * alpha[mi][rr] + ts;
            }
        }

        // ---- O += P.V ; warp: rows [wm,wm+64), d [wc*16,+16) ----
#pragma unroll
        for (int ks = 0; ks < 16; ks++) {
            const int kb = ks * 8;
            uint32_t a[4][4];
#pragma unroll
            for (int mi = 0; mi < 4; mi++) ldsm4(a[mi], pa[mi] + ks * 32);
#pragma unroll
            for (int ni = 0; ni < 2; ni++) {
                const int n = wc * 16 + ni * 8 + g;
                uint32_t b[2] = { sm.Vs[kb + tg][n], sm.Vs[kb + tg + 4][n] };
#pragma unroll
                for (int mi = 0; mi < 4; mi++)
                    mma8(acc_o[mi][ni], a[mi], b);
            }
        }
    }

    // ---- epilogue: O /= l, scatter to g_attn[b, s, h*64 + d] ----
#pragma unroll
    for (int mi = 0; mi < 4; mi++) {
#pragma unroll
        for (int rr = 0; rr < 2; rr++) {
            const int row = wm + mi * 16 + rr * 8 + g;
            const float inv = 1.0f / l_st[mi][rr];
#pragma unroll
            for (int ni = 0; ni < 2; ni++) {
                const int d = wc * 16 + ni * 8 + 2 * tg;
                float2 o;
                o.x = acc_o[mi][ni][rr * 2 + 0] * inv;
                o.y = acc_o[mi][ni][rr * 2 + 1] * inv;
                *(float2*)&g_attn[(size_t)(bb * S_ + i0 + row) * D_ + h * 64 + d] = o;
            }
        }
    }
}

// ------------------------------------------------------------------------
extern "C" void kernel_launch(void* const* d_in, const int* in_sizes, int n_in,
                              void* d_out, int out_size)
{
    const float* q    = (const float*)d_in[0];
    const float* k    = (const float*)d_in[1];
    const float* v    = (const float*)d_in[2];
    const int*   mask = (const int*)  d_in[3];
    const float* Wq   = (const float*)d_in[4];
    const float* bq   = (const float*)d_in[5];
    const float* Wk   = (const float*)d_in[6];
    const float* bk   = (const float*)d_in[7];
    const float* Wv   = (const float*)d_in[8];
    const float* bv   = (const float*)d_in[9];
    const float* Wo   = (const float*)d_in[10];
    const float* bo   = (const float*)d_in[11];
    float* out = (float*)d_out;

    cudaFuncSetAttribute(proj_tf32<0>, cudaFuncAttributeMaxDynamicSharedMemorySize, (int)sizeof(ProjSmem));
    cudaFuncSetAttribute(proj_tf32<1>, cudaFuncAttributeMaxDynamicSharedMemorySize, (int)sizeof(ProjSmem));
    cudaFuncSetAttribute(proj_tf32<2>, cudaFuncAttributeMaxDynamicSharedMemorySize, (int)sizeof(ProjSmem));
    cudaFuncSetAttribute(proj_tf32<3>, cudaFuncAttributeMaxDynamicSharedMemorySize, (int)sizeof(ProjSmem));
    cudaFuncSetAttribute(flash_tf32,   cudaFuncAttributeMaxDynamicSharedMemorySize, (int)sizeof(FlashSmem));

    dim3 gproj(D_ / 128, M_ / 128);          // (8, 32)
    proj_tf32<0><<<gproj, 512, sizeof(ProjSmem)>>>(q, Wq, bq, nullptr);
    proj_tf32<1><<<gproj, 512, sizeof(ProjSmem)>>>(k, Wk, bk, nullptr);
    proj_tf32<2><<<gproj, 512, sizeof(ProjSmem)>>>(v, Wv, bv, nullptr);

    dim3 gfl(S_ / 128, BH_);                 // (16, 32) = 512 blocks
    flash_tf32<<<gfl, 256, sizeof(FlashSmem)>>>(mask);

    proj_tf32<3><<<gproj, 512, sizeof(ProjSmem)>>>(nullptr, Wo, bo, out);
}